// round 15
// baseline (speedup 1.0000x reference)
#include <cuda_runtime.h>
#include <cuda_bf16.h>

#define N_NODES 50000
#define N_EDGES 800000
#define D 128

typedef unsigned long long u64;

// ---------------------------------------------------------------------------
// Scratch (__device__ globals per allocation-free rule)
// ---------------------------------------------------------------------------
__device__ __align__(16) float g_agg[N_NODES * D];   // 25.6 MB
__device__ __align__(16) float g_deg[N_NODES];

// ---------------------------------------------------------------------------
// K1: zero accumulation scratch
// ---------------------------------------------------------------------------
__global__ void zero_kernel() {
    int i = blockIdx.x * blockDim.x + threadIdx.x;
    const int n4 = (N_NODES * D) / 4;
    if (i < n4) ((float4*)g_agg)[i] = make_float4(0.f, 0.f, 0.f, 0.f);
    if (i < N_NODES) g_deg[i] = 0.f;
}

// ---------------------------------------------------------------------------
// K3: edge scatter, FOUR edges per warp (MLP=4) — R11 proven configuration.
// ---------------------------------------------------------------------------
__device__ __forceinline__ void red_add_v4(float* addr, float4 v) {
    asm volatile("red.global.add.v4.f32 [%0], {%1, %2, %3, %4};"
                 :: "l"(addr), "f"(v.x), "f"(v.y), "f"(v.z), "f"(v.w)
                 : "memory");
}

__global__ void __launch_bounds__(256) scatter_kernel(
    const float* __restrict__ x,
    const int* __restrict__ ei)
{
    unsigned tid = blockIdx.x * blockDim.x + threadIdx.x;
    unsigned w = tid >> 5;
    unsigned lane = tid & 31;
    unsigned base = w * 4;
    if (base >= N_EDGES) return;

    int4 s4 = *(const int4*)(ei + base);
    int4 d4 = *(const int4*)(ei + N_EDGES + base);

    bool ok0 = (unsigned)s4.x < N_NODES && (unsigned)d4.x < N_NODES;
    bool ok1 = (unsigned)s4.y < N_NODES && (unsigned)d4.y < N_NODES;
    bool ok2 = (unsigned)s4.z < N_NODES && (unsigned)d4.z < N_NODES;
    bool ok3 = (unsigned)s4.w < N_NODES && (unsigned)d4.w < N_NODES;

    const unsigned off = lane * 4;
    float4 v0, v1, v2, v3;
    if (ok0) v0 = *(const float4*)(x + (size_t)s4.x * D + off);
    if (ok1) v1 = *(const float4*)(x + (size_t)s4.y * D + off);
    if (ok2) v2 = *(const float4*)(x + (size_t)s4.z * D + off);
    if (ok3) v3 = *(const float4*)(x + (size_t)s4.w * D + off);

    if (ok0) red_add_v4(g_agg + (size_t)d4.x * D + off, v0);
    if (ok1) red_add_v4(g_agg + (size_t)d4.y * D + off, v1);
    if (ok2) red_add_v4(g_agg + (size_t)d4.z * D + off, v2);
    if (ok3) red_add_v4(g_agg + (size_t)d4.w * D + off, v3);

    if (lane == 0) {
        if (ok0) atomicAdd(&g_deg[d4.x], 1.0f);
        if (ok1) atomicAdd(&g_deg[d4.y], 1.0f);
        if (ok2) atomicAdd(&g_deg[d4.z], 1.0f);
        if (ok3) atomicAdd(&g_deg[d4.w], 1.0f);
    }
}

// ---------------------------------------------------------------------------
// K2/K4: half-GEMMs, staged K (two 64-k chunks), smem 50.4 KB.
// NOW 4 CTAs/SM (launch_bounds minBlocks=4 -> 64-reg budget; smem fits:
// 4 x 50.4 KB = 201.6 KB < 227 KB). Inner loop identical to R11.
//   PHASE 0:  out = x @ W_r^T + b_l          (pre-activation)
//   PHASE 1:  out = relu((agg/deg) @ W_l^T + out)
// ---------------------------------------------------------------------------
#define TN 64
#define KS 64
#define WSTR 132
#define OFF_W 0
#define OFF_T (KS * WSTR)
#define OFF_S (OFF_T + KS * TN)
#define H_SMEM_FLOATS (OFF_S + TN)
#define H_SMEM_BYTES  (H_SMEM_FLOATS * 4)    // 50,432 B
#define GEMM_GRID ((N_NODES + TN - 1) / TN)  // 782

__device__ __forceinline__ void ffma2(u64& d, u64 a, u64 b) {
    asm("fma.rn.f32x2 %0, %1, %2, %0;" : "+l"(d) : "l"(a), "l"(b));
}

template <int PHASE>
__global__ void __launch_bounds__(256, 4) gemm_half(
    const float* __restrict__ x,       // used in PHASE 0 only
    const float* __restrict__ W,       // PHASE 0: W_r, PHASE 1: W_l
    const float* __restrict__ b_l,     // used in PHASE 0 only
    float* __restrict__ out)
{
    extern __shared__ float sm[];
    float* Wsm   = sm + OFF_W;
    float* tileT = sm + OFF_T;
    float* ssm   = sm + OFF_S;

    const int t = threadIdx.x;
    const int nodeBase = blockIdx.x * TN;
    const float* src = (PHASE == 0) ? x : (const float*)g_agg;

    if (PHASE == 1) {
        if (t < TN) {
            int n = nodeBase + t;
            float dg = (n < N_NODES) ? g_deg[n] : 1.0f;
            ssm[t] = 1.0f / fmaxf(dg, 1.0f);
        }
        __syncthreads();
    }

    const int c0 = (t & 31) * 4;
    const int n0 = (t >> 5) * 8;

    u64 acc[4][4];
    #pragma unroll
    for (int p = 0; p < 4; p++)
        #pragma unroll
        for (int c = 0; c < 4; c++) acc[p][c] = 0ull;

    #pragma unroll
    for (int stage = 0; stage < 2; stage++) {
        const int kOff = stage * KS;

        // W stage slice transposed: Wsm[k][c] = W[c][kOff + k]
        #pragma unroll 4
        for (int l = t; l < D * KS; l += 256) {
            int c = l >> 6;
            int k = l & 63;
            Wsm[k * WSTR + c] = W[c * D + kOff + k];
        }

        // Tile stage slice k-major: 64 nodes x 64 k
        #pragma unroll
        for (int i = 0; i < 4; i++) {
            int f = t + i * 256;
            int node = f & 63;
            int kq   = f >> 6;
            int gn = nodeBase + node;
            float4 v = make_float4(0.f, 0.f, 0.f, 0.f);
            if (gn < N_NODES) {
                v = *(const float4*)(src + (size_t)gn * D + kOff + kq * 4);
                if (PHASE == 1) {
                    float s = ssm[node];
                    v.x *= s; v.y *= s; v.z *= s; v.w *= s;
                }
            }
            int k0 = kq * 4;
            tileT[(k0 + 0) * TN + node] = v.x;
            tileT[(k0 + 1) * TN + node] = v.y;
            tileT[(k0 + 2) * TN + node] = v.z;
            tileT[(k0 + 3) * TN + node] = v.w;
        }
        __syncthreads();

        const float* aBase = tileT + n0;
        const float* wBase = Wsm + c0;

        #pragma unroll 4
        for (int k = 0; k < KS; k++) {
            u64 a01, a23, a45, a67;
            asm("ld.shared.v2.b64 {%0, %1}, [%2];"
                : "=l"(a01), "=l"(a23) : "l"(aBase + k * TN));
            asm("ld.shared.v2.b64 {%0, %1}, [%2];"
                : "=l"(a45), "=l"(a67) : "l"(aBase + k * TN + 4));

            float4 w = *(const float4*)(wBase + k * WSTR);
            u64 wx, wy, wz, ww;
            asm("mov.b64 %0, {%1, %1};" : "=l"(wx) : "f"(w.x));
            asm("mov.b64 %0, {%1, %1};" : "=l"(wy) : "f"(w.y));
            asm("mov.b64 %0, {%1, %1};" : "=l"(wz) : "f"(w.z));
            asm("mov.b64 %0, {%1, %1};" : "=l"(ww) : "f"(w.w));

            ffma2(acc[0][0], a01, wx); ffma2(acc[0][1], a01, wy);
            ffma2(acc[0][2], a01, wz); ffma2(acc[0][3], a01, ww);
            ffma2(acc[1][0], a23, wx); ffma2(acc[1][1], a23, wy);
            ffma2(acc[1][2], a23, wz); ffma2(acc[1][3], a23, ww);
            ffma2(acc[2][0], a45, wx); ffma2(acc[2][1], a45, wy);
            ffma2(acc[2][2], a45, wz); ffma2(acc[2][3], a45, ww);
            ffma2(acc[3][0], a67, wx); ffma2(acc[3][1], a67, wy);
            ffma2(acc[3][2], a67, wz); ffma2(acc[3][3], a67, ww);
        }
        __syncthreads();
    }

    float4 bias = make_float4(0.f, 0.f, 0.f, 0.f);
    if (PHASE == 0) bias = *(const float4*)&b_l[c0];

    #pragma unroll
    for (int p = 0; p < 4; p++) {
        float lo[4], hi[4];
        #pragma unroll
        for (int c = 0; c < 4; c++) {
            asm("mov.b64 {%0, %1}, %2;"
                : "=f"(lo[c]), "=f"(hi[c]) : "l"(acc[p][c]));
        }
        int nA = nodeBase + n0 + 2 * p;
        int nB = nA + 1;
        if (nA < N_NODES) {
            float4 o;
            if (PHASE == 0) {
                o.x = lo[0] + bias.x; o.y = lo[1] + bias.y;
                o.z = lo[2] + bias.z; o.w = lo[3] + bias.w;
            } else {
                float4 prev = *(const float4*)&out[(size_t)nA * D + c0];
                o.x = fmaxf(lo[0] + prev.x, 0.f);
                o.y = fmaxf(lo[1] + prev.y, 0.f);
                o.z = fmaxf(lo[2] + prev.z, 0.f);
                o.w = fmaxf(lo[3] + prev.w, 0.f);
            }
            *(float4*)&out[(size_t)nA * D + c0] = o;
        }
        if (nB < N_NODES) {
            float4 o;
            if (PHASE == 0) {
                o.x = hi[0] + bias.x; o.y = hi[1] + bias.y;
                o.z = hi[2] + bias.z; o.w = hi[3] + bias.w;
            } else {
                float4 prev = *(const float4*)&out[(size_t)nB * D + c0];
                o.x = fmaxf(hi[0] + prev.x, 0.f);
                o.y = fmaxf(hi[1] + prev.y, 0.f);
                o.z = fmaxf(hi[2] + prev.z, 0.f);
                o.w = fmaxf(hi[3] + prev.w, 0.f);
            }
            *(float4*)&out[(size_t)nB * D + c0] = o;
        }
    }
}

// ---------------------------------------------------------------------------
extern "C" void kernel_launch(void* const* d_in, const int* in_sizes, int n_in,
                              void* d_out, int out_size) {
    const float* x   = (const float*)d_in[0];
    const int*   ei  = (const int*)d_in[1];
    const float* W_l = (const float*)d_in[2];
    const float* b_l = (const float*)d_in[3];
    const float* W_r = (const float*)d_in[4];
    float*       out = (float*)d_out;

    cudaFuncSetAttribute(gemm_half<0>,
                         cudaFuncAttributeMaxDynamicSharedMemorySize, H_SMEM_BYTES);
    cudaFuncSetAttribute(gemm_half<1>,
                         cudaFuncAttributeMaxDynamicSharedMemorySize, H_SMEM_BYTES);

    zero_kernel<<<6250, 256>>>();
    // x-half GEMM does not depend on aggregation; run it before scatter
    gemm_half<0><<<GEMM_GRID, 256, H_SMEM_BYTES>>>(x, W_r, b_l, out);
    // 800000 edges / 4 per warp / 8 warps per block = 25000 blocks
    scatter_kernel<<<25000, 256>>>(x, ei);
    gemm_half<1><<<GEMM_GRID, 256, H_SMEM_BYTES>>>(x, W_l, b_l, out);
}

// round 17
// speedup vs baseline: 1.0910x; 1.0910x over previous
#include <cuda_runtime.h>
#include <cuda_bf16.h>

#define N_NODES 50000
#define N_EDGES 800000
#define D 128

typedef unsigned long long u64;

// ---------------------------------------------------------------------------
// Scratch (__device__ globals per allocation-free rule)
// ---------------------------------------------------------------------------
__device__ __align__(16) float g_agg[N_NODES * D];   // 25.6 MB
__device__ __align__(16) float g_deg[N_NODES];

// ---------------------------------------------------------------------------
// K1: zero accumulation scratch
// ---------------------------------------------------------------------------
__global__ void zero_kernel() {
    int i = blockIdx.x * blockDim.x + threadIdx.x;
    const int n4 = (N_NODES * D) / 4;
    if (i < n4) ((float4*)g_agg)[i] = make_float4(0.f, 0.f, 0.f, 0.f);
    if (i < N_NODES) g_deg[i] = 0.f;
}

// ---------------------------------------------------------------------------
// K2: edge scatter, FOUR edges per warp (MLP=4) — R11 proven configuration.
// ---------------------------------------------------------------------------
__device__ __forceinline__ void red_add_v4(float* addr, float4 v) {
    asm volatile("red.global.add.v4.f32 [%0], {%1, %2, %3, %4};"
                 :: "l"(addr), "f"(v.x), "f"(v.y), "f"(v.z), "f"(v.w)
                 : "memory");
}

__global__ void __launch_bounds__(256) scatter_kernel(
    const float* __restrict__ x,
    const int* __restrict__ ei)
{
    unsigned tid = blockIdx.x * blockDim.x + threadIdx.x;
    unsigned w = tid >> 5;
    unsigned lane = tid & 31;
    unsigned base = w * 4;
    if (base >= N_EDGES) return;

    int4 s4 = *(const int4*)(ei + base);
    int4 d4 = *(const int4*)(ei + N_EDGES + base);

    bool ok0 = (unsigned)s4.x < N_NODES && (unsigned)d4.x < N_NODES;
    bool ok1 = (unsigned)s4.y < N_NODES && (unsigned)d4.y < N_NODES;
    bool ok2 = (unsigned)s4.z < N_NODES && (unsigned)d4.z < N_NODES;
    bool ok3 = (unsigned)s4.w < N_NODES && (unsigned)d4.w < N_NODES;

    const unsigned off = lane * 4;
    float4 v0, v1, v2, v3;
    if (ok0) v0 = *(const float4*)(x + (size_t)s4.x * D + off);
    if (ok1) v1 = *(const float4*)(x + (size_t)s4.y * D + off);
    if (ok2) v2 = *(const float4*)(x + (size_t)s4.z * D + off);
    if (ok3) v3 = *(const float4*)(x + (size_t)s4.w * D + off);

    if (ok0) red_add_v4(g_agg + (size_t)d4.x * D + off, v0);
    if (ok1) red_add_v4(g_agg + (size_t)d4.y * D + off, v1);
    if (ok2) red_add_v4(g_agg + (size_t)d4.z * D + off, v2);
    if (ok3) red_add_v4(g_agg + (size_t)d4.w * D + off, v3);

    if (lane == 0) {
        if (ok0) atomicAdd(&g_deg[d4.x], 1.0f);
        if (ok1) atomicAdd(&g_deg[d4.y], 1.0f);
        if (ok2) atomicAdd(&g_deg[d4.z], 1.0f);
        if (ok3) atomicAdd(&g_deg[d4.w], 1.0f);
    }
}

// ---------------------------------------------------------------------------
// K3: MONOLITHIC gemm, K=256 in FOUR 64-k stages (same 50.4 KB smem and
// proven 8-node x 4-col FFMA2 inner loop as R11; 3 CTAs/SM).
//   stages 0,1: src = agg (scaled by 1/deg), W = W_l
//   stages 2,3: src = x,                     W = W_r
//   epilogue:   out = relu(acc + b_l)        (single write, no RMW)
// ---------------------------------------------------------------------------
#define TN 64
#define KS 64
#define WSTR 132
#define OFF_W 0
#define OFF_T (KS * WSTR)
#define OFF_S (OFF_T + KS * TN)
#define H_SMEM_FLOATS (OFF_S + TN)
#define H_SMEM_BYTES  (H_SMEM_FLOATS * 4)    // 50,432 B
#define GEMM_GRID ((N_NODES + TN - 1) / TN)  // 782

__device__ __forceinline__ void ffma2(u64& d, u64 a, u64 b) {
    asm("fma.rn.f32x2 %0, %1, %2, %0;" : "+l"(d) : "l"(a), "l"(b));
}

__global__ void __launch_bounds__(256, 3) gemm_mono(
    const float* __restrict__ x,
    const float* __restrict__ W_l,
    const float* __restrict__ b_l,
    const float* __restrict__ W_r,
    float* __restrict__ out)
{
    extern __shared__ float sm[];
    float* Wsm   = sm + OFF_W;
    float* tileT = sm + OFF_T;
    float* ssm   = sm + OFF_S;

    const int t = threadIdx.x;
    const int nodeBase = blockIdx.x * TN;

    if (t < TN) {
        int n = nodeBase + t;
        float dg = (n < N_NODES) ? g_deg[n] : 1.0f;
        ssm[t] = 1.0f / fmaxf(dg, 1.0f);
    }
    __syncthreads();

    const int c0 = (t & 31) * 4;
    const int n0 = (t >> 5) * 8;

    u64 acc[4][4];
    #pragma unroll
    for (int p = 0; p < 4; p++)
        #pragma unroll
        for (int c = 0; c < 4; c++) acc[p][c] = 0ull;

    #pragma unroll
    for (int stage = 0; stage < 4; stage++) {
        const int half = stage >> 1;              // 0: agg/W_l, 1: x/W_r
        const int kOff = (stage & 1) * KS;        // offset within the half
        const float* W   = half ? W_r : W_l;
        const float* src = half ? x : (const float*)g_agg;

        // W stage slice transposed: Wsm[k][c] = W[c][kOff + k]
        #pragma unroll 4
        for (int l = t; l < D * KS; l += 256) {
            int c = l >> 6;
            int k = l & 63;
            Wsm[k * WSTR + c] = W[c * D + kOff + k];
        }

        // Tile stage slice k-major: 64 nodes x 64 k
        #pragma unroll
        for (int i = 0; i < 4; i++) {
            int f = t + i * 256;
            int node = f & 63;
            int kq   = f >> 6;
            int gn = nodeBase + node;
            float4 v = make_float4(0.f, 0.f, 0.f, 0.f);
            if (gn < N_NODES) {
                v = *(const float4*)(src + (size_t)gn * D + kOff + kq * 4);
                if (half == 0) {
                    float s = ssm[node];
                    v.x *= s; v.y *= s; v.z *= s; v.w *= s;
                }
            }
            int k0 = kq * 4;
            tileT[(k0 + 0) * TN + node] = v.x;
            tileT[(k0 + 1) * TN + node] = v.y;
            tileT[(k0 + 2) * TN + node] = v.z;
            tileT[(k0 + 3) * TN + node] = v.w;
        }
        __syncthreads();

        const float* aBase = tileT + n0;
        const float* wBase = Wsm + c0;

        #pragma unroll 4
        for (int k = 0; k < KS; k++) {
            u64 a01, a23, a45, a67;
            asm("ld.shared.v2.b64 {%0, %1}, [%2];"
                : "=l"(a01), "=l"(a23) : "l"(aBase + k * TN));
            asm("ld.shared.v2.b64 {%0, %1}, [%2];"
                : "=l"(a45), "=l"(a67) : "l"(aBase + k * TN + 4));

            float4 w = *(const float4*)(wBase + k * WSTR);
            u64 wx, wy, wz, ww;
            asm("mov.b64 %0, {%1, %1};" : "=l"(wx) : "f"(w.x));
            asm("mov.b64 %0, {%1, %1};" : "=l"(wy) : "f"(w.y));
            asm("mov.b64 %0, {%1, %1};" : "=l"(wz) : "f"(w.z));
            asm("mov.b64 %0, {%1, %1};" : "=l"(ww) : "f"(w.w));

            ffma2(acc[0][0], a01, wx); ffma2(acc[0][1], a01, wy);
            ffma2(acc[0][2], a01, wz); ffma2(acc[0][3], a01, ww);
            ffma2(acc[1][0], a23, wx); ffma2(acc[1][1], a23, wy);
            ffma2(acc[1][2], a23, wz); ffma2(acc[1][3], a23, ww);
            ffma2(acc[2][0], a45, wx); ffma2(acc[2][1], a45, wy);
            ffma2(acc[2][2], a45, wz); ffma2(acc[2][3], a45, ww);
            ffma2(acc[3][0], a67, wx); ffma2(acc[3][1], a67, wy);
            ffma2(acc[3][2], a67, wz); ffma2(acc[3][3], a67, ww);
        }
        __syncthreads();
    }

    const float4 bias = *(const float4*)&b_l[c0];

    #pragma unroll
    for (int p = 0; p < 4; p++) {
        float lo[4], hi[4];
        #pragma unroll
        for (int c = 0; c < 4; c++) {
            asm("mov.b64 {%0, %1}, %2;"
                : "=f"(lo[c]), "=f"(hi[c]) : "l"(acc[p][c]));
        }
        int nA = nodeBase + n0 + 2 * p;
        int nB = nA + 1;
        if (nA < N_NODES) {
            float4 o;
            o.x = fmaxf(lo[0] + bias.x, 0.f);
            o.y = fmaxf(lo[1] + bias.y, 0.f);
            o.z = fmaxf(lo[2] + bias.z, 0.f);
            o.w = fmaxf(lo[3] + bias.w, 0.f);
            *(float4*)&out[(size_t)nA * D + c0] = o;
        }
        if (nB < N_NODES) {
            float4 o;
            o.x = fmaxf(hi[0] + bias.x, 0.f);
            o.y = fmaxf(hi[1] + bias.y, 0.f);
            o.z = fmaxf(hi[2] + bias.z, 0.f);
            o.w = fmaxf(hi[3] + bias.w, 0.f);
            *(float4*)&out[(size_t)nB * D + c0] = o;
        }
    }
}

// ---------------------------------------------------------------------------
extern "C" void kernel_launch(void* const* d_in, const int* in_sizes, int n_in,
                              void* d_out, int out_size) {
    const float* x   = (const float*)d_in[0];
    const int*   ei  = (const int*)d_in[1];
    const float* W_l = (const float*)d_in[2];
    const float* b_l = (const float*)d_in[3];
    const float* W_r = (const float*)d_in[4];
    float*       out = (float*)d_out;

    cudaFuncSetAttribute(gemm_mono,
                         cudaFuncAttributeMaxDynamicSharedMemorySize, H_SMEM_BYTES);

    zero_kernel<<<6250, 256>>>();
    scatter_kernel<<<25000, 256>>>(x, ei);
    gemm_mono<<<GEMM_GRID, 256, H_SMEM_BYTES>>>(x, W_l, b_l, W_r, out);
}